// round 15
// baseline (speedup 1.0000x reference)
#include <cuda_runtime.h>
#include <cuda_fp16.h>
#include <stdint.h>

#define BB 8
#define SS 2048
#define EE 256
#define AA 256
#define MM (BB*SS)   // 16384 rows
#define NT (SS/64)   // 32 key tiles

// fp16 q/k/v scratch; q pre-scaled by log2(e)/16
__device__ __half g_q[MM*AA];
__device__ __half g_k[MM*AA];
__device__ __half g_v[MM*AA];
// pre-converted, pre-swizzled weights: [z][kc] chunks of 32KB
__device__ __half g_w[3*EE*AA];

__device__ __forceinline__ void mma_f16(float d[4], const uint32_t a[4],
                                        uint32_t b0, uint32_t b1) {
    asm volatile(
        "mma.sync.aligned.m16n8k16.row.col.f32.f16.f16.f32 "
        "{%0,%1,%2,%3}, {%4,%5,%6,%7}, {%8,%9}, {%0,%1,%2,%3};"
        : "+f"(d[0]), "+f"(d[1]), "+f"(d[2]), "+f"(d[3])
        : "r"(a[0]), "r"(a[1]), "r"(a[2]), "r"(a[3]), "r"(b0), "r"(b1));
}
__device__ __forceinline__ void ldsm_x4(uint32_t r[4], uint32_t addr) {
    asm volatile("ldmatrix.sync.aligned.m8n8.x4.shared.b16 {%0,%1,%2,%3}, [%4];"
                 : "=r"(r[0]), "=r"(r[1]), "=r"(r[2]), "=r"(r[3]) : "r"(addr));
}
__device__ __forceinline__ void ldsm_x4_t(uint32_t r[4], uint32_t addr) {
    asm volatile("ldmatrix.sync.aligned.m8n8.x4.trans.shared.b16 {%0,%1,%2,%3}, [%4];"
                 : "=r"(r[0]), "=r"(r[1]), "=r"(r[2]), "=r"(r[3]) : "r"(addr));
}
__device__ __forceinline__ void cp_async16(uint32_t smem_addr, const void* gptr) {
    asm volatile("cp.async.cg.shared.global [%0], [%1], 16;\n"
                 :: "r"(smem_addr), "l"(gptr));
}
__device__ __forceinline__ uint32_t ex2_f16x2(uint32_t x) {
    uint32_t y;
    asm("ex2.approx.f16x2 %0, %1;" : "=r"(y) : "r"(x));
    return y;
}
__device__ __forceinline__ uint32_t packh2(float lo, float hi) {
    __half2 h = __floats2half2_rn(lo, hi);
    return *reinterpret_cast<uint32_t*>(&h);
}

#define BAR_SYNC(id)   asm volatile("bar.sync %0, 256;"   :: "r"(id) : "memory")
#define BAR_ARRIVE(id) asm volatile("bar.arrive %0, 256;" :: "r"(id) : "memory")
#define BAR_SYNC_PROD() asm volatile("bar.sync 5, 128;" ::: "memory")
#define MEMBAR_CTA()   asm volatile("membar.cta;" ::: "memory")

// SW128-style XOR swizzle
#define SWZ(o) ((o) ^ (((o) >> 3) & 0x70))

__device__ __forceinline__ uint32_t toff(int r, int colh) {
    uint32_t o = ((uint32_t)(r >> 3) + (uint32_t)(colh >> 6) * 8u) * 1024u
               + (uint32_t)(r & 7) * 128u + (uint32_t)(colh & 63) * 2u;
    return SWZ(o);
}
__device__ __forceinline__ uint32_t toff128(int r, int colh) {
    uint32_t o = ((uint32_t)(r >> 3) + (uint32_t)(colh >> 6) * 16u) * 1024u
               + (uint32_t)(r & 7) * 128u + (uint32_t)(colh & 63) * 2u;
    return SWZ(o);
}

// ---------------------------------------------------------------------------
// convw: fp32 W -> fp16, pre-swizzled 32KB chunks [z*4 + kc]
// ---------------------------------------------------------------------------
__global__ __launch_bounds__(256) void convw_kernel(
    const float* __restrict__ Wq, const float* __restrict__ Wk,
    const float* __restrict__ Wv)
{
    int idx = blockIdx.x * 256 + threadIdx.x;
    int z   = idx >> 14;
    int e   = idx & 16383;
    int k   = e >> 6;
    int c4  = e & 63;
    const float* W = (z == 0) ? Wq : (z == 1) ? Wk : Wv;
    float4 v = __ldg(reinterpret_cast<const float4*>(W + (size_t)k * AA + c4 * 4));
    uint2 u = { packh2(v.x, v.y), packh2(v.z, v.w) };
    int chunk = k >> 6, r = k & 63;
    char* dst = reinterpret_cast<char*>(g_w) + (size_t)(z * 4 + chunk) * 32768
              + toff(r, c4 * 4);
    *reinterpret_cast<uint2*>(dst) = u;
}

// ---------------------------------------------------------------------------
// Fused projection: x staged once, W streamed via cp.async (pre-swizzled g_w)
// ---------------------------------------------------------------------------
#define PJ_X  0
#define PJ_W0 (128*512)
#define PJ_W1 (PJ_W0 + 32768)
#define PJ_TOTAL (PJ_W1 + 32768)

__global__ __launch_bounds__(512) void proj_kernel(
    const float* __restrict__ x,
    const float* __restrict__ bq, const float* __restrict__ bk,
    const float* __restrict__ bv)
{
    extern __shared__ char psm[];
    const uint32_t sbx = (uint32_t)__cvta_generic_to_shared(psm) + PJ_X;
    const uint32_t sw0 = (uint32_t)__cvta_generic_to_shared(psm) + PJ_W0;
    const uint32_t sw1 = (uint32_t)__cvta_generic_to_shared(psm) + PJ_W1;

    const int tid  = threadIdx.x;
    const int warp = tid >> 5;
    const int lane = tid & 31;
    const int rg   = warp & 7;
    const int ch   = warp >> 3;
    const int row0 = blockIdx.x * 128;

    const char* gw = reinterpret_cast<const char*>(g_w);

    #pragma unroll
    for (int i = 0; i < 4; ++i) {
        uint32_t off = (uint32_t)(tid + i * 512) * 16u;
        cp_async16(sw0 + off, gw + off);
    }
    asm volatile("cp.async.commit_group;\n");
    #pragma unroll
    for (int i = 0; i < 4; ++i) {
        uint32_t off = (uint32_t)(tid + i * 512) * 16u;
        cp_async16(sw1 + off, gw + 32768 + off);
    }
    asm volatile("cp.async.commit_group;\n");

    #pragma unroll
    for (int i = 0; i < 16; ++i) {
        int idx = tid + i * 512;
        int r  = idx >> 6;
        int c4 = idx & 63;
        float4 v = __ldg(reinterpret_cast<const float4*>(
            &x[(size_t)(row0 + r) * EE + c4 * 4]));
        uint2 u = { packh2(v.x, v.y), packh2(v.z, v.w) };
        *reinterpret_cast<uint2*>(psm + PJ_X + toff128(r, c4 * 4)) = u;
    }

    const float* bs[3]   = { bq, bk, bv };
    __half*      outs[3] = { g_q, g_k, g_v };

    float o[16][4];
    #pragma unroll
    for (int ng = 0; ng < 16; ++ng)
        #pragma unroll
        for (int j = 0; j < 4; ++j) o[ng][j] = 0.f;

    for (int c = 0; c < 12; ++c) {
        asm volatile("cp.async.wait_group 1;\n");
        __syncthreads();

        const uint32_t wbuf = (c & 1) ? sw1 : sw0;
        const int kc = c & 3;

        #pragma unroll
        for (int kst = 0; kst < 4; ++kst) {
            uint32_t af[4];
            ldsm_x4(af, sbx + toff128(rg * 16 + (lane & 15),
                                      kc * 64 + kst * 16 + (lane >> 4) * 8));
            int wrow = kst * 16 + (lane & 15);
            #pragma unroll
            for (int nt2 = 0; nt2 < 8; ++nt2) {
                uint32_t bf[4];
                ldsm_x4_t(bf, wbuf + toff(wrow, ch * 128 + nt2 * 16 + (lane >> 4) * 8));
                mma_f16(o[nt2*2],     af, bf[0], bf[1]);
                mma_f16(o[nt2*2 + 1], af, bf[2], bf[3]);
            }
        }

        if (kc == 3) {
            const int z = c >> 2;
            const float sc = (z == 0) ? 0.09016994f : 1.0f;
            const float* bias = bs[z];
            __half* out = outs[z];
            int ra = row0 + rg * 16 + (lane >> 2);
            int rb = ra + 8;
            #pragma unroll
            for (int ng = 0; ng < 16; ++ng) {
                int col = ch * 128 + ng * 8 + 2 * (lane & 3);
                float b0 = __ldg(&bias[col]);
                float b1 = __ldg(&bias[col + 1]);
                __half2 ha = __floats2half2_rn((o[ng][0] + b0) * sc, (o[ng][1] + b1) * sc);
                __half2 hb = __floats2half2_rn((o[ng][2] + b0) * sc, (o[ng][3] + b1) * sc);
                *reinterpret_cast<__half2*>(&out[(size_t)ra * AA + col]) = ha;
                *reinterpret_cast<__half2*>(&out[(size_t)rb * AA + col]) = hb;
                o[ng][0] = 0.f; o[ng][1] = 0.f; o[ng][2] = 0.f; o[ng][3] = 0.f;
            }
        }

        __syncthreads();

        if (c + 2 < 12) {
            const char* src = gw + (size_t)(c + 2) * 32768;
            uint32_t dst = (c & 1) ? sw1 : sw0;
            #pragma unroll
            for (int i = 0; i < 4; ++i) {
                uint32_t off = (uint32_t)(tid + i * 512) * 16u;
                cp_async16(dst + off, src + off);
            }
        }
        asm volatile("cp.async.commit_group;\n");
    }
}

// ---------------------------------------------------------------------------
// Warp-specialized flash attention: 256 threads / 8 warps.
// Warps 0-3 = producers (QK + mask + exp + P write, K double-buffer, Q frags
// in regs). Warps 4-7 = consumers (PV + ones-MMA l, V double-buffer, O regs).
// P double-buffered; named-barrier ping-pong. Producer-only barrier (id 5)
// orders all producer K(t) reads before the K(t+2) same-buffer prefetch.
// ---------------------------------------------------------------------------
#define SM_K0   0
#define SM_K1   (SM_K0 + 64*512)
#define SM_V0   (SM_K1 + 64*512)
#define SM_V1   (SM_V0 + 64*512)
#define SM_P0   (SM_V1 + 64*512)
#define SM_P1   (SM_P0 + 8192)
#define SM_TOTAL (SM_P1 + 8192)

#define ONESH2 0x3C003C00u

__global__ __launch_bounds__(256) void attn_kernel(
    const int* __restrict__ mask, float* __restrict__ out)
{
    extern __shared__ char smem[];
    const uint32_t sb = (uint32_t)__cvta_generic_to_shared(smem);

    const int tid  = threadIdx.x;
    const int warp = tid >> 5;
    const int lane = tid & 31;
    const int rg   = warp & 3;          // 16-row group (both roles)
    const int role = warp >> 2;         // 0 = producer (QK), 1 = consumer (PV)
    const int b    = blockIdx.y;
    const int q0   = blockIdx.x * 64;

    const int qra = rg * 16 + (lane >> 2);
    const int b8  = (lane >> 3) & 1;

    // XOR-addressing bases
    const uint32_t KA0 = (uint32_t)(b8 * 1024 + (lane & 7) * 128
                     + (((lane >> 4) * 16) ^ ((lane & 7) * 16)));
    const uint32_t VA0 = KA0;   // same formula (V read covers all 256 cols)
    const uint32_t PRA0 = (uint32_t)(rg * 2048 + b8 * 1024 + (lane & 7) * 128
                     + (((lane >> 4) * 16) ^ ((lane & 7) * 16)));
    const uint32_t PWA0 = (uint32_t)(rg * 2048 + (lane >> 2) * 128
                     + (((lane & 3) * 4) ^ ((lane >> 2) * 16)));

    // per-role 16-chunk prefetch offsets (tile = 2048 chunks / 128 threads)
    const int rtid = tid & 127;
    uint32_t soff16[16];
    #pragma unroll
    for (int i = 0; i < 16; ++i) {
        int idx = rtid + i * 128;
        soff16[i] = toff(idx >> 5, (idx & 31) * 8);
    }

    const char* gkb = reinterpret_cast<const char*>(g_k + (size_t)(b * SS) * AA);
    const char* gvb = reinterpret_cast<const char*>(g_v + (size_t)(b * SS) * AA);

    // ---- prologue: stage Q into K0 (all threads) ----
    {
        const char* gq = reinterpret_cast<const char*>(g_q + (size_t)(b * SS + q0) * AA);
        #pragma unroll
        for (int i = 0; i < 8; ++i) {
            int idx = tid + i * 256;
            uint32_t so = toff(idx >> 5, (idx & 31) * 8);
            cp_async16(sb + SM_K0 + so, gq + (size_t)(idx >> 5) * 512 + (idx & 31) * 16);
        }
        asm volatile("cp.async.commit_group;\n");
        asm volatile("cp.async.wait_group 0;\n");
        __syncthreads();
    }

    // producers extract Q fragments
    uint32_t qf[16][4];
    if (role == 0) {
        int qrow = rg * 16 + (lane & 15);
        #pragma unroll
        for (int ks16 = 0; ks16 < 16; ++ks16)
            ldsm_x4(qf[ks16], sb + SM_K0 + toff(qrow, ks16 * 16 + (lane >> 4) * 8));
    }
    __syncthreads();   // Q reads done before K0 refill

    if (role == 0) {
        // =================== PRODUCER: QK + softmax ===================
        // prefetch K(0), K(1)
        #pragma unroll
        for (int i = 0; i < 16; ++i) {
            int idx = rtid + i * 128;
            size_t go = (size_t)(idx >> 5) * 512 + (idx & 31) * 16;
            cp_async16(sb + SM_K0 + soff16[i], gkb + go);
        }
        asm volatile("cp.async.commit_group;\n");
        #pragma unroll
        for (int i = 0; i < 16; ++i) {
            int idx = rtid + i * 128;
            size_t go = (size_t)(idx >> 5) * 512 + (idx & 31) * 16;
            cp_async16(sb + SM_K1 + soff16[i], gkb + 32768 + go);
        }
        asm volatile("cp.async.commit_group;\n");

        const int* mpa = mask + ((size_t)(b * SS) + q0 + qra) * SS + 2 * (lane & 3);
        const int* mpb = mpa + (size_t)8 * SS;
        const float NEG = -60000.f;

        for (int t = 0; t < NT; ++t) {
            if (t >= 2) BAR_SYNC(3 + (t & 1));          // P buf free
            asm volatile("cp.async.wait_group 1;\n");    // K(t) ready
            __syncwarp();

            // mask loads (overlap with QK MMAs)
            const int* ma = mpa + t * 64;
            const int* mb = mpb + t * 64;
            int2 mva[8], mvb[8];
            #pragma unroll
            for (int g = 0; g < 8; ++g) {
                mva[g] = __ldg(reinterpret_cast<const int2*>(ma + g * 8));
                mvb[g] = __ldg(reinterpret_cast<const int2*>(mb + g * 8));
            }

            const uint32_t kcur = sb + ((t & 1) ? SM_K1 : SM_K0);

            float s[8][4];
            #pragma unroll
            for (int g = 0; g < 8; ++g)
                #pragma unroll
                for (int j = 0; j < 4; ++j) s[g][j] = 0.f;

            #pragma unroll
            for (int ks16 = 0; ks16 < 16; ++ks16) {
                uint32_t xorc = (uint32_t)(((ks16 >> 2) * 8192) | ((ks16 & 3) * 32));
                #pragma unroll
                for (int kg = 0; kg < 4; ++kg) {
                    uint32_t kf[4];
                    ldsm_x4(kf, kcur + (KA0 ^ xorc ^ (uint32_t)(kg * 2048)));
                    mma_f16(s[kg*2],     qf[ks16], kf[0], kf[2]);
                    mma_f16(s[kg*2 + 1], qf[ks16], kf[1], kf[3]);
                }
            }

            // all producer warps done reading K(t) before same-buffer refill
            BAR_SYNC_PROD();

            // prefetch K(t+2) into buf[t&1]
            if (t + 2 < NT) {
                const char* gk = gkb + (size_t)(t + 2) * 32768;
                uint32_t kb = sb + ((t & 1) ? SM_K1 : SM_K0);
                #pragma unroll
                for (int i = 0; i < 16; ++i) {
                    int idx = rtid + i * 128;
                    size_t go = (size_t)(idx >> 5) * 512 + (idx & 31) * 16;
                    cp_async16(kb + soff16[i], gk + go);
                }
            }
            asm volatile("cp.async.commit_group;\n");

            // mask-select + ex2 + P write
            char* pw = smem + ((t & 1) ? SM_P1 : SM_P0);
            #pragma unroll
            for (int g = 0; g < 8; ++g) {
                uint32_t pa = ex2_f16x2(packh2(mva[g].x ? s[g][0] : NEG,
                                               mva[g].y ? s[g][1] : NEG));
                uint32_t pb = ex2_f16x2(packh2(mvb[g].x ? s[g][2] : NEG,
                                               mvb[g].y ? s[g][3] : NEG));
                uint32_t wa = PWA0 ^ (uint32_t)(g * 16);
                *reinterpret_cast<uint32_t*>(pw + wa)           = pa;
                *reinterpret_cast<uint32_t*>(pw + (wa ^ 1024u)) = pb;
            }
            MEMBAR_CTA();
            BAR_ARRIVE(1 + (t & 1));   // P(t) full
        }
    } else {
        // =================== CONSUMER: PV + l ===================
        // prefetch V(0)
        #pragma unroll
        for (int i = 0; i < 16; ++i) {
            int idx = rtid + i * 128;
            size_t go = (size_t)(idx >> 5) * 512 + (idx & 31) * 16;
            cp_async16(sb + SM_V0 + soff16[i], gvb + go);
        }
        asm volatile("cp.async.commit_group;\n");

        float o[32][4];
        #pragma unroll
        for (int ng = 0; ng < 32; ++ng)
            #pragma unroll
            for (int j = 0; j < 4; ++j) o[ng][j] = 0.f;
        float ol[4] = {0.f, 0.f, 0.f, 0.f};

        for (int t = 0; t < NT; ++t) {
            BAR_SYNC(1 + (t & 1));   // P(t) full

            // prefetch V(t+1) into buf[(t+1)&1] (V(t-1) reads all complete:
            // every consumer warp passed this iteration's bar.sync)
            if (t + 1 < NT) {
                const char* gv = gvb + (size_t)(t + 1) * 32768;
                uint32_t vb = sb + (((t + 1) & 1) ? SM_V1 : SM_V0);
                #pragma unroll
                for (int i = 0; i < 16; ++i) {
                    int idx = rtid + i * 128;
                    size_t go = (size_t)(idx >> 5) * 512 + (idx & 31) * 16;
                    cp_async16(vb + soff16[i], gv + go);
                }
            }
            asm volatile("cp.async.commit_group;\n");
            asm volatile("cp.async.wait_group 1;\n");   // V(t) ready
            __syncwarp();

            const uint32_t vcur = sb + ((t & 1) ? SM_V1 : SM_V0);
            const uint32_t pcur = sb + ((t & 1) ? SM_P1 : SM_P0);

            #pragma unroll
            for (int kst = 0; kst < 4; ++kst) {
                uint32_t af[4];
                ldsm_x4(af, pcur + (PRA0 ^ (uint32_t)(kst * 32)));
                #pragma unroll
                for (int nt = 0; nt < 16; ++nt) {
                    uint32_t bf[4];
                    ldsm_x4_t(bf, vcur + (VA0 ^ (uint32_t)((kst * 2048)
                                         | ((nt >> 2) * 8192) | ((nt & 3) * 32))));
                    mma_f16(o[nt*2],     af, bf[0], bf[1]);
                    mma_f16(o[nt*2 + 1], af, bf[2], bf[3]);
                }
                mma_f16(ol, af, ONESH2, ONESH2);
            }
            MEMBAR_CTA();
            BAR_ARRIVE(3 + (t & 1));   // P(t) consumed
        }

        // ---- normalize + write (consumer owns the full 256 cols) ----
        float inva = 1.f / ol[0];
        float invb = 1.f / ol[2];
        size_t base_a = ((size_t)(b * SS + q0 + qra)) * AA;
        size_t base_b = base_a + (size_t)8 * AA;
        #pragma unroll
        for (int ng = 0; ng < 32; ++ng) {
            int col = ng * 8 + 2 * (lane & 3);
            float2 va = { o[ng][0] * inva, o[ng][1] * inva };
            float2 vb = { o[ng][2] * invb, o[ng][3] * invb };
            *reinterpret_cast<float2*>(&out[base_a + col]) = va;
            *reinterpret_cast<float2*>(&out[base_b + col]) = vb;
        }
    }
}

// ---------------------------------------------------------------------------
extern "C" void kernel_launch(void* const* d_in, const int* in_sizes, int n_in,
                              void* d_out, int out_size)
{
    const float* x   = (const float*)d_in[0];
    const int*   msk = (const int*)  d_in[1];
    const float* Wq  = (const float*)d_in[2];
    const float* bq  = (const float*)d_in[3];
    const float* Wk  = (const float*)d_in[4];
    const float* bk  = (const float*)d_in[5];
    const float* Wv  = (const float*)d_in[6];
    const float* bv  = (const float*)d_in[7];
    float* out = (float*)d_out;

    convw_kernel<<<192, 256>>>(Wq, Wk, Wv);

    cudaFuncSetAttribute(proj_kernel,
                         cudaFuncAttributeMaxDynamicSharedMemorySize,
                         PJ_TOTAL);
    proj_kernel<<<MM / 128, 512, PJ_TOTAL>>>(x, bq, bk, bv);

    cudaFuncSetAttribute(attn_kernel,
                         cudaFuncAttributeMaxDynamicSharedMemorySize,
                         SM_TOTAL);
    dim3 agrid(SS / 64, BB);
    attn_kernel<<<agrid, 256, SM_TOTAL>>>(msk, out);
}

// round 16
// speedup vs baseline: 1.0914x; 1.0914x over previous
#include <cuda_runtime.h>
#include <cuda_fp16.h>
#include <stdint.h>

#define BB 8
#define SS 2048
#define EE 256
#define AA 256
#define MM (BB*SS)   // 16384 rows
#define NT (SS/64)   // 32 key tiles

// fp16 q/k/v scratch; q pre-scaled by log2(e)/16
__device__ __half g_q[MM*AA];
__device__ __half g_k[MM*AA];
__device__ __half g_v[MM*AA];
// pre-converted, pre-swizzled weights: [z][kc] chunks of 32KB
__device__ __half g_w[3*EE*AA];

__device__ __forceinline__ void mma_f16(float d[4], const uint32_t a[4],
                                        uint32_t b0, uint32_t b1) {
    asm volatile(
        "mma.sync.aligned.m16n8k16.row.col.f32.f16.f16.f32 "
        "{%0,%1,%2,%3}, {%4,%5,%6,%7}, {%8,%9}, {%0,%1,%2,%3};"
        : "+f"(d[0]), "+f"(d[1]), "+f"(d[2]), "+f"(d[3])
        : "r"(a[0]), "r"(a[1]), "r"(a[2]), "r"(a[3]), "r"(b0), "r"(b1));
}
__device__ __forceinline__ void ldsm_x4(uint32_t r[4], uint32_t addr) {
    asm volatile("ldmatrix.sync.aligned.m8n8.x4.shared.b16 {%0,%1,%2,%3}, [%4];"
                 : "=r"(r[0]), "=r"(r[1]), "=r"(r[2]), "=r"(r[3]) : "r"(addr));
}
__device__ __forceinline__ void ldsm_x4_t(uint32_t r[4], uint32_t addr) {
    asm volatile("ldmatrix.sync.aligned.m8n8.x4.trans.shared.b16 {%0,%1,%2,%3}, [%4];"
                 : "=r"(r[0]), "=r"(r[1]), "=r"(r[2]), "=r"(r[3]) : "r"(addr));
}
__device__ __forceinline__ void cp_async16(uint32_t smem_addr, const void* gptr) {
    asm volatile("cp.async.cg.shared.global [%0], [%1], 16;\n"
                 :: "r"(smem_addr), "l"(gptr));
}
__device__ __forceinline__ uint32_t ex2_f16x2(uint32_t x) {
    uint32_t y;
    asm("ex2.approx.f16x2 %0, %1;" : "=r"(y) : "r"(x));
    return y;
}
__device__ __forceinline__ uint32_t packh2(float lo, float hi) {
    __half2 h = __floats2half2_rn(lo, hi);
    return *reinterpret_cast<uint32_t*>(&h);
}

// SW128-style XOR swizzle
#define SWZ(o) ((o) ^ (((o) >> 3) & 0x70))

__device__ __forceinline__ uint32_t toff(int r, int colh) {
    uint32_t o = ((uint32_t)(r >> 3) + (uint32_t)(colh >> 6) * 8u) * 1024u
               + (uint32_t)(r & 7) * 128u + (uint32_t)(colh & 63) * 2u;
    return SWZ(o);
}
__device__ __forceinline__ uint32_t toff128(int r, int colh) {
    uint32_t o = ((uint32_t)(r >> 3) + (uint32_t)(colh >> 6) * 16u) * 1024u
               + (uint32_t)(r & 7) * 128u + (uint32_t)(colh & 63) * 2u;
    return SWZ(o);
}

// ---------------------------------------------------------------------------
// convw: fp32 W -> fp16, pre-swizzled 32KB chunks [z*4 + kc]
// ---------------------------------------------------------------------------
__global__ __launch_bounds__(256) void convw_kernel(
    const float* __restrict__ Wq, const float* __restrict__ Wk,
    const float* __restrict__ Wv)
{
    int idx = blockIdx.x * 256 + threadIdx.x;
    int z   = idx >> 14;
    int e   = idx & 16383;
    int k   = e >> 6;
    int c4  = e & 63;
    const float* W = (z == 0) ? Wq : (z == 1) ? Wk : Wv;
    float4 v = __ldg(reinterpret_cast<const float4*>(W + (size_t)k * AA + c4 * 4));
    uint2 u = { packh2(v.x, v.y), packh2(v.z, v.w) };
    int chunk = k >> 6, r = k & 63;
    char* dst = reinterpret_cast<char*>(g_w) + (size_t)(z * 4 + chunk) * 32768
              + toff(r, c4 * 4);
    *reinterpret_cast<uint2*>(dst) = u;
}

// ---------------------------------------------------------------------------
// Fused projection: x staged once, W streamed via cp.async (pre-swizzled g_w)
// ---------------------------------------------------------------------------
#define PJ_X  0
#define PJ_W0 (128*512)
#define PJ_W1 (PJ_W0 + 32768)
#define PJ_TOTAL (PJ_W1 + 32768)

__global__ __launch_bounds__(512) void proj_kernel(
    const float* __restrict__ x,
    const float* __restrict__ bq, const float* __restrict__ bk,
    const float* __restrict__ bv)
{
    extern __shared__ char psm[];
    const uint32_t sbx = (uint32_t)__cvta_generic_to_shared(psm) + PJ_X;
    const uint32_t sw0 = (uint32_t)__cvta_generic_to_shared(psm) + PJ_W0;
    const uint32_t sw1 = (uint32_t)__cvta_generic_to_shared(psm) + PJ_W1;

    const int tid  = threadIdx.x;
    const int warp = tid >> 5;
    const int lane = tid & 31;
    const int rg   = warp & 7;
    const int ch   = warp >> 3;
    const int row0 = blockIdx.x * 128;

    const char* gw = reinterpret_cast<const char*>(g_w);

    #pragma unroll
    for (int i = 0; i < 4; ++i) {
        uint32_t off = (uint32_t)(tid + i * 512) * 16u;
        cp_async16(sw0 + off, gw + off);
    }
    asm volatile("cp.async.commit_group;\n");
    #pragma unroll
    for (int i = 0; i < 4; ++i) {
        uint32_t off = (uint32_t)(tid + i * 512) * 16u;
        cp_async16(sw1 + off, gw + 32768 + off);
    }
    asm volatile("cp.async.commit_group;\n");

    #pragma unroll
    for (int i = 0; i < 16; ++i) {
        int idx = tid + i * 512;
        int r  = idx >> 6;
        int c4 = idx & 63;
        float4 v = __ldg(reinterpret_cast<const float4*>(
            &x[(size_t)(row0 + r) * EE + c4 * 4]));
        uint2 u = { packh2(v.x, v.y), packh2(v.z, v.w) };
        *reinterpret_cast<uint2*>(psm + PJ_X + toff128(r, c4 * 4)) = u;
    }

    const float* bs[3]   = { bq, bk, bv };
    __half*      outs[3] = { g_q, g_k, g_v };

    float o[16][4];
    #pragma unroll
    for (int ng = 0; ng < 16; ++ng)
        #pragma unroll
        for (int j = 0; j < 4; ++j) o[ng][j] = 0.f;

    for (int c = 0; c < 12; ++c) {
        asm volatile("cp.async.wait_group 1;\n");
        __syncthreads();

        const uint32_t wbuf = (c & 1) ? sw1 : sw0;
        const int kc = c & 3;

        #pragma unroll
        for (int kst = 0; kst < 4; ++kst) {
            uint32_t af[4];
            ldsm_x4(af, sbx + toff128(rg * 16 + (lane & 15),
                                      kc * 64 + kst * 16 + (lane >> 4) * 8));
            int wrow = kst * 16 + (lane & 15);
            #pragma unroll
            for (int nt2 = 0; nt2 < 8; ++nt2) {
                uint32_t bf[4];
                ldsm_x4_t(bf, wbuf + toff(wrow, ch * 128 + nt2 * 16 + (lane >> 4) * 8));
                mma_f16(o[nt2*2],     af, bf[0], bf[1]);
                mma_f16(o[nt2*2 + 1], af, bf[2], bf[3]);
            }
        }

        if (kc == 3) {
            const int z = c >> 2;
            const float sc = (z == 0) ? 0.09016994f : 1.0f;
            const float* bias = bs[z];
            __half* out = outs[z];
            int ra = row0 + rg * 16 + (lane >> 2);
            int rb = ra + 8;
            #pragma unroll
            for (int ng = 0; ng < 16; ++ng) {
                int col = ch * 128 + ng * 8 + 2 * (lane & 3);
                float b0 = __ldg(&bias[col]);
                float b1 = __ldg(&bias[col + 1]);
                __half2 ha = __floats2half2_rn((o[ng][0] + b0) * sc, (o[ng][1] + b1) * sc);
                __half2 hb = __floats2half2_rn((o[ng][2] + b0) * sc, (o[ng][3] + b1) * sc);
                *reinterpret_cast<__half2*>(&out[(size_t)ra * AA + col]) = ha;
                *reinterpret_cast<__half2*>(&out[(size_t)rb * AA + col]) = hb;
                o[ng][0] = 0.f; o[ng][1] = 0.f; o[ng][2] = 0.f; o[ng][3] = 0.f;
            }
        }

        __syncthreads();

        if (c + 2 < 12) {
            const char* src = gw + (size_t)(c + 2) * 32768;
            uint32_t dst = (c & 1) ? sw1 : sw0;
            #pragma unroll
            for (int i = 0; i < 4; ++i) {
                uint32_t off = (uint32_t)(tid + i * 512) * 16u;
                cp_async16(dst + off, src + off);
            }
        }
        asm volatile("cp.async.commit_group;\n");
    }
}

// ---------------------------------------------------------------------------
// Flash attention (R12 structure + register PV for own key half):
// 256 threads / 8 warps (rg = warp&3, ch = warp>>2). QK 16x32.
// PV split: own 32 keys from REGISTER P-frags (before barrier),
// sibling's 32 keys from smem P (after barrier).
// ---------------------------------------------------------------------------
#define SM_Q    0
#define SM_K0   (SM_Q  + 64*512)
#define SM_K1   (SM_K0 + 64*512)
#define SM_V0   (SM_K1 + 64*512)
#define SM_V1   (SM_V0 + 64*512)
#define SM_P    (SM_V1 + 64*512)
#define SM_TOTAL (SM_P + 64*128)

#define ONESH2 0x3C003C00u

__global__ __launch_bounds__(256) void attn_kernel(
    const int* __restrict__ mask, float* __restrict__ out)
{
    extern __shared__ char smem[];
    const uint32_t sb = (uint32_t)__cvta_generic_to_shared(smem);

    const int tid  = threadIdx.x;
    const int warp = tid >> 5;
    const int lane = tid & 31;
    const int rg   = warp & 3;      // 16-row group
    const int ch   = warp >> 2;     // key/column half (0..1)
    const int b    = blockIdx.y;
    const int q0   = blockIdx.x * 64;

    const int qra = rg * 16 + (lane >> 2);
    const int qrb = qra + 8;
    const int b8  = (lane >> 3) & 1;

    // ---- XOR-addressing bases (loop-invariant) ----
    const uint32_t KA0 = (uint32_t)((ch * 4 + b8) * 1024 + (lane & 7) * 128
                     + (((lane >> 4) * 16) ^ ((lane & 7) * 16)));
    const uint32_t VA0 = (uint32_t)(ch * 16384 + b8 * 1024 + (lane & 7) * 128
                     + (((lane >> 4) * 16) ^ ((lane & 7) * 16)));
    const uint32_t PRA0 = (uint32_t)(rg * 2048 + b8 * 1024 + (lane & 7) * 128
                     + (((lane >> 4) * 16) ^ ((lane & 7) * 16)));
    const uint32_t PWA0 = (uint32_t)(rg * 2048 + (lane >> 2) * 128
                     + ((((lane & 3) * 4) ^ ((lane >> 2) * 16)) ^ (ch * 64)));

    uint32_t soff[8];
    #pragma unroll
    for (int i = 0; i < 8; ++i) {
        int idx = tid + i * 256;
        soff[i] = toff(idx >> 5, (idx & 31) * 8);
    }

    const int* mpa = mask + ((size_t)(b * SS) + q0 + qra) * SS + ch * 32 + 2 * (lane & 3);
    const int* mpb = mpa + (size_t)8 * SS;

    // ---- stage Q + K0 + V0 ----
    {
        const char* gq = reinterpret_cast<const char*>(g_q + (size_t)(b * SS + q0) * AA);
        const char* gk = reinterpret_cast<const char*>(g_k + (size_t)(b * SS) * AA);
        const char* gv = reinterpret_cast<const char*>(g_v + (size_t)(b * SS) * AA);
        #pragma unroll
        for (int i = 0; i < 8; ++i) {
            int idx = tid + i * 256;
            size_t go = (size_t)(idx >> 5) * 512 + (idx & 31) * 16;
            cp_async16(sb + SM_Q  + soff[i], gq + go);
            cp_async16(sb + SM_K0 + soff[i], gk + go);
            cp_async16(sb + SM_V0 + soff[i], gv + go);
        }
        asm volatile("cp.async.commit_group;\n");
        asm volatile("cp.async.wait_group 0;\n");
        __syncthreads();
    }

    // ---- Q fragments persist in registers (64 regs) ----
    uint32_t qf[16][4];
    {
        int qrow = rg * 16 + (lane & 15);
        #pragma unroll
        for (int ks16 = 0; ks16 < 16; ++ks16)
            ldsm_x4(qf[ks16], sb + SM_Q + toff(qrow, ks16 * 16 + (lane >> 4) * 8));
    }

    float o[16][4];
    #pragma unroll
    for (int ng = 0; ng < 16; ++ng)
        #pragma unroll
        for (int j = 0; j < 4; ++j) o[ng][j] = 0.f;
    float ol[4] = {0.f, 0.f, 0.f, 0.f};
    const float NEG = -60000.f;

    for (int t = 0; t < NT; ++t) {
        asm volatile("cp.async.wait_group 0;\n");
        __syncthreads();

        // ---- prefetch next K/V ----
        if (t + 1 < NT) {
            const char* gk = reinterpret_cast<const char*>(
                g_k + (size_t)(b * SS + (t + 1) * 64) * AA);
            const char* gv = reinterpret_cast<const char*>(
                g_v + (size_t)(b * SS + (t + 1) * 64) * AA);
            uint32_t kb = sb + (((t + 1) & 1) ? SM_K1 : SM_K0);
            uint32_t vb = sb + (((t + 1) & 1) ? SM_V1 : SM_V0);
            #pragma unroll
            for (int i = 0; i < 8; ++i) {
                int idx = tid + i * 256;
                size_t go = (size_t)(idx >> 5) * 512 + (idx & 31) * 16;
                cp_async16(kb + soff[i], gk + go);
                cp_async16(vb + soff[i], gv + go);
            }
            asm volatile("cp.async.commit_group;\n");
        }

        // ---- mask prefetch ----
        const int* ma = mpa + t * 64;
        const int* mb = mpb + t * 64;
        int2 mva[4], mvb[4];
        #pragma unroll
        for (int g = 0; g < 4; ++g) {
            mva[g] = __ldg(reinterpret_cast<const int2*>(ma + g * 8));
            mvb[g] = __ldg(reinterpret_cast<const int2*>(mb + g * 8));
        }

        const uint32_t kcur = sb + ((t & 1) ? SM_K1 : SM_K0);
        const uint32_t vcur = sb + ((t & 1) ? SM_V1 : SM_V0);

        // ---- S = Q K^T : 16 rows x 32 keys per warp (4 indep chains) ----
        float s[4][4];
        #pragma unroll
        for (int g = 0; g < 4; ++g)
            #pragma unroll
            for (int j = 0; j < 4; ++j) s[g][j] = 0.f;

        #pragma unroll
        for (int ks16 = 0; ks16 < 16; ++ks16) {
            uint32_t xorc = (uint32_t)(((ks16 >> 2) * 8192) | ((ks16 & 3) * 32));
            uint32_t kf0[4], kf1[4];
            ldsm_x4(kf0, kcur + (KA0 ^ xorc));
            ldsm_x4(kf1, kcur + (KA0 ^ xorc ^ 2048u));
            mma_f16(s[0], qf[ks16], kf0[0], kf0[2]);
            mma_f16(s[1], qf[ks16], kf0[1], kf0[3]);
            mma_f16(s[2], qf[ks16], kf1[0], kf1[2]);
            mma_f16(s[3], qf[ks16], kf1[1], kf1[3]);
        }

        // ---- mask-select, ex2, store P; KEEP packed frags in regs ----
        uint32_t pp[4][2];   // [g][0]=rows r..r+7 pack, [1]=rows r+8..r+15
        #pragma unroll
        for (int g = 0; g < 4; ++g) {
            uint32_t pa = ex2_f16x2(packh2(mva[g].x ? s[g][0] : NEG,
                                           mva[g].y ? s[g][1] : NEG));
            uint32_t pb = ex2_f16x2(packh2(mvb[g].x ? s[g][2] : NEG,
                                           mvb[g].y ? s[g][3] : NEG));
            uint32_t wa = PWA0 ^ (uint32_t)(g * 16);
            *reinterpret_cast<uint32_t*>(smem + SM_P + wa)           = pa;
            *reinterpret_cast<uint32_t*>(smem + SM_P + (wa ^ 1024u)) = pb;
            pp[g][0] = pa;
            pp[g][1] = pb;
        }

        // ---- PV over OWN 32 keys: A-frags straight from registers ----
        #pragma unroll
        for (int j = 0; j < 2; ++j) {
            uint32_t af[4] = { pp[2*j][0], pp[2*j][1], pp[2*j+1][0], pp[2*j+1][1] };
            uint32_t kst = (uint32_t)(ch * 2 + j);
            #pragma unroll
            for (int nt = 0; nt < 8; ++nt) {
                uint32_t bf[4];
                ldsm_x4_t(bf, vcur + (VA0 ^ (uint32_t)((kst * 2048)
                                     | ((nt >> 2) * 8192) | ((nt & 3) * 32))));
                mma_f16(o[nt*2],     af, bf[0], bf[1]);
                mma_f16(o[nt*2 + 1], af, bf[2], bf[3]);
            }
            mma_f16(ol, af, ONESH2, ONESH2);
        }

        __syncthreads();   // sibling P halves visible

        // ---- PV over SIBLING's 32 keys: A-frags from smem P ----
        #pragma unroll
        for (int j = 0; j < 2; ++j) {
            uint32_t kst = (uint32_t)((1 - ch) * 2 + j);
            uint32_t af[4];
            ldsm_x4(af, sb + SM_P + (PRA0 ^ (kst * 32u)));
            #pragma unroll
            for (int nt = 0; nt < 8; ++nt) {
                uint32_t bf[4];
                ldsm_x4_t(bf, vcur + (VA0 ^ (uint32_t)((kst * 2048)
                                     | ((nt >> 2) * 8192) | ((nt & 3) * 32))));
                mma_f16(o[nt*2],     af, bf[0], bf[1]);
                mma_f16(o[nt*2 + 1], af, bf[2], bf[3]);
            }
            mma_f16(ol, af, ONESH2, ONESH2);
        }
        // next iteration's top sync orders P reuse
    }

    // ---- normalize + write ----
    float inva = 1.f / ol[0];
    float invb = 1.f / ol[2];
    size_t base_a = ((size_t)(b * SS + q0 + qra)) * AA;
    size_t base_b = base_a + (size_t)8 * AA;
    #pragma unroll
    for (int ng = 0; ng < 16; ++ng) {
        int col = ch * 128 + ng * 8 + 2 * (lane & 3);
        float2 va = { o[ng][0] * inva, o[ng][1] * inva };
        float2 vb = { o[ng][2] * invb, o[ng][3] * invb };
        *reinterpret_cast<float2*>(&out[base_a + col]) = va;
        *reinterpret_cast<float2*>(&out[base_b + col]) = vb;
    }
}

// ---------------------------------------------------------------------------
extern "C" void kernel_launch(void* const* d_in, const int* in_sizes, int n_in,
                              void* d_out, int out_size)
{
    const float* x   = (const float*)d_in[0];
    const int*   msk = (const int*)  d_in[1];
    const float* Wq  = (const float*)d_in[2];
    const float* bq  = (const float*)d_in[3];
    const float* Wk  = (const float*)d_in[4];
    const float* bk  = (const float*)d_in[5];
    const float* Wv  = (const float*)d_in[6];
    const float* bv  = (const float*)d_in[7];
    float* out = (float*)d_out;

    convw_kernel<<<192, 256>>>(Wq, Wk, Wv);

    cudaFuncSetAttribute(proj_kernel,
                         cudaFuncAttributeMaxDynamicSharedMemorySize,
                         PJ_TOTAL);
    proj_kernel<<<MM / 128, 512, PJ_TOTAL>>>(x, bq, bk, bv);

    cudaFuncSetAttribute(attn_kernel,
                         cudaFuncAttributeMaxDynamicSharedMemorySize,
                         SM_TOTAL);
    dim3 agrid(SS / 64, BB);
    attn_kernel<<<agrid, 256, SM_TOTAL>>>(msk, out);
}

// round 17
// speedup vs baseline: 1.1598x; 1.0627x over previous
#include <cuda_runtime.h>
#include <cuda_fp16.h>
#include <stdint.h>

#define BB 8
#define SS 2048
#define EE 256
#define AA 256
#define MM (BB*SS)   // 16384 rows
#define NT (SS/64)   // 32 key tiles

// fp16 q/k/v scratch; q pre-scaled by log2(e)/16
__device__ __half g_q[MM*AA];
__device__ __half g_k[MM*AA];
__device__ __half g_v[MM*AA];
// pre-converted, pre-swizzled weights: [z][kc] chunks of 32KB
__device__ __half g_w[3*EE*AA];

__device__ __forceinline__ void mma_f16(float d[4], const uint32_t a[4],
                                        uint32_t b0, uint32_t b1) {
    asm volatile(
        "mma.sync.aligned.m16n8k16.row.col.f32.f16.f16.f32 "
        "{%0,%1,%2,%3}, {%4,%5,%6,%7}, {%8,%9}, {%0,%1,%2,%3};"
        : "+f"(d[0]), "+f"(d[1]), "+f"(d[2]), "+f"(d[3])
        : "r"(a[0]), "r"(a[1]), "r"(a[2]), "r"(a[3]), "r"(b0), "r"(b1));
}
__device__ __forceinline__ void ldsm_x4(uint32_t r[4], uint32_t addr) {
    asm volatile("ldmatrix.sync.aligned.m8n8.x4.shared.b16 {%0,%1,%2,%3}, [%4];"
                 : "=r"(r[0]), "=r"(r[1]), "=r"(r[2]), "=r"(r[3]) : "r"(addr));
}
__device__ __forceinline__ void ldsm_x4_t(uint32_t r[4], uint32_t addr) {
    asm volatile("ldmatrix.sync.aligned.m8n8.x4.trans.shared.b16 {%0,%1,%2,%3}, [%4];"
                 : "=r"(r[0]), "=r"(r[1]), "=r"(r[2]), "=r"(r[3]) : "r"(addr));
}
__device__ __forceinline__ void cp_async16(uint32_t smem_addr, const void* gptr) {
    asm volatile("cp.async.cg.shared.global [%0], [%1], 16;\n"
                 :: "r"(smem_addr), "l"(gptr));
}
__device__ __forceinline__ uint32_t ex2_f16x2(uint32_t x) {
    uint32_t y;
    asm("ex2.approx.f16x2 %0, %1;" : "=r"(y) : "r"(x));
    return y;
}
__device__ __forceinline__ uint32_t packh2(float lo, float hi) {
    __half2 h = __floats2half2_rn(lo, hi);
    return *reinterpret_cast<uint32_t*>(&h);
}

// SW128-style XOR swizzle
#define SWZ(o) ((o) ^ (((o) >> 3) & 0x70))

__device__ __forceinline__ uint32_t toff(int r, int colh) {
    uint32_t o = ((uint32_t)(r >> 3) + (uint32_t)(colh >> 6) * 8u) * 1024u
               + (uint32_t)(r & 7) * 128u + (uint32_t)(colh & 63) * 2u;
    return SWZ(o);
}
__device__ __forceinline__ uint32_t toff128(int r, int colh) {
    uint32_t o = ((uint32_t)(r >> 3) + (uint32_t)(colh >> 6) * 16u) * 1024u
               + (uint32_t)(r & 7) * 128u + (uint32_t)(colh & 63) * 2u;
    return SWZ(o);
}

// ---------------------------------------------------------------------------
// convw: fp32 W -> fp16, pre-swizzled 32KB chunks [z*4 + kc]
// ---------------------------------------------------------------------------
__global__ __launch_bounds__(256) void convw_kernel(
    const float* __restrict__ Wq, const float* __restrict__ Wk,
    const float* __restrict__ Wv)
{
    int idx = blockIdx.x * 256 + threadIdx.x;
    int z   = idx >> 14;
    int e   = idx & 16383;
    int k   = e >> 6;
    int c4  = e & 63;
    const float* W = (z == 0) ? Wq : (z == 1) ? Wk : Wv;
    float4 v = __ldg(reinterpret_cast<const float4*>(W + (size_t)k * AA + c4 * 4));
    uint2 u = { packh2(v.x, v.y), packh2(v.z, v.w) };
    int chunk = k >> 6, r = k & 63;
    char* dst = reinterpret_cast<char*>(g_w) + (size_t)(z * 4 + chunk) * 32768
              + toff(r, c4 * 4);
    *reinterpret_cast<uint2*>(dst) = u;
}

// ---------------------------------------------------------------------------
// Fused projection: x staged once, W streamed via cp.async (pre-swizzled g_w)
// ---------------------------------------------------------------------------
#define PJ_X  0
#define PJ_W0 (128*512)
#define PJ_W1 (PJ_W0 + 32768)
#define PJ_TOTAL (PJ_W1 + 32768)

__global__ __launch_bounds__(512) void proj_kernel(
    const float* __restrict__ x,
    const float* __restrict__ bq, const float* __restrict__ bk,
    const float* __restrict__ bv)
{
    extern __shared__ char psm[];
    const uint32_t sbx = (uint32_t)__cvta_generic_to_shared(psm) + PJ_X;
    const uint32_t sw0 = (uint32_t)__cvta_generic_to_shared(psm) + PJ_W0;
    const uint32_t sw1 = (uint32_t)__cvta_generic_to_shared(psm) + PJ_W1;

    const int tid  = threadIdx.x;
    const int warp = tid >> 5;
    const int lane = tid & 31;
    const int rg   = warp & 7;
    const int ch   = warp >> 3;
    const int row0 = blockIdx.x * 128;

    const char* gw = reinterpret_cast<const char*>(g_w);

    #pragma unroll
    for (int i = 0; i < 4; ++i) {
        uint32_t off = (uint32_t)(tid + i * 512) * 16u;
        cp_async16(sw0 + off, gw + off);
    }
    asm volatile("cp.async.commit_group;\n");
    #pragma unroll
    for (int i = 0; i < 4; ++i) {
        uint32_t off = (uint32_t)(tid + i * 512) * 16u;
        cp_async16(sw1 + off, gw + 32768 + off);
    }
    asm volatile("cp.async.commit_group;\n");

    #pragma unroll
    for (int i = 0; i < 16; ++i) {
        int idx = tid + i * 512;
        int r  = idx >> 6;
        int c4 = idx & 63;
        float4 v = __ldg(reinterpret_cast<const float4*>(
            &x[(size_t)(row0 + r) * EE + c4 * 4]));
        uint2 u = { packh2(v.x, v.y), packh2(v.z, v.w) };
        *reinterpret_cast<uint2*>(psm + PJ_X + toff128(r, c4 * 4)) = u;
    }

    const float* bs[3]   = { bq, bk, bv };
    __half*      outs[3] = { g_q, g_k, g_v };

    float o[16][4];
    #pragma unroll
    for (int ng = 0; ng < 16; ++ng)
        #pragma unroll
        for (int j = 0; j < 4; ++j) o[ng][j] = 0.f;

    for (int c = 0; c < 12; ++c) {
        asm volatile("cp.async.wait_group 1;\n");
        __syncthreads();

        const uint32_t wbuf = (c & 1) ? sw1 : sw0;
        const int kc = c & 3;

        #pragma unroll
        for (int kst = 0; kst < 4; ++kst) {
            uint32_t af[4];
            ldsm_x4(af, sbx + toff128(rg * 16 + (lane & 15),
                                      kc * 64 + kst * 16 + (lane >> 4) * 8));
            int wrow = kst * 16 + (lane & 15);
            #pragma unroll
            for (int nt2 = 0; nt2 < 8; ++nt2) {
                uint32_t bf[4];
                ldsm_x4_t(bf, wbuf + toff(wrow, ch * 128 + nt2 * 16 + (lane >> 4) * 8));
                mma_f16(o[nt2*2],     af, bf[0], bf[1]);
                mma_f16(o[nt2*2 + 1], af, bf[2], bf[3]);
            }
        }

        if (kc == 3) {
            const int z = c >> 2;
            const float sc = (z == 0) ? 0.09016994f : 1.0f;
            const float* bias = bs[z];
            __half* out = outs[z];
            int ra = row0 + rg * 16 + (lane >> 2);
            int rb = ra + 8;
            #pragma unroll
            for (int ng = 0; ng < 16; ++ng) {
                int col = ch * 128 + ng * 8 + 2 * (lane & 3);
                float b0 = __ldg(&bias[col]);
                float b1 = __ldg(&bias[col + 1]);
                __half2 ha = __floats2half2_rn((o[ng][0] + b0) * sc, (o[ng][1] + b1) * sc);
                __half2 hb = __floats2half2_rn((o[ng][2] + b0) * sc, (o[ng][3] + b1) * sc);
                *reinterpret_cast<__half2*>(&out[(size_t)ra * AA + col]) = ha;
                *reinterpret_cast<__half2*>(&out[(size_t)rb * AA + col]) = hb;
                o[ng][0] = 0.f; o[ng][1] = 0.f; o[ng][2] = 0.f; o[ng][3] = 0.f;
            }
        }

        __syncthreads();

        if (c + 2 < 12) {
            const char* src = gw + (size_t)(c + 2) * 32768;
            uint32_t dst = (c & 1) ? sw1 : sw0;
            #pragma unroll
            for (int i = 0; i < 4; ++i) {
                uint32_t off = (uint32_t)(tid + i * 512) * 16u;
                cp_async16(dst + off, src + off);
            }
        }
        asm volatile("cp.async.commit_group;\n");
    }
}

// ---------------------------------------------------------------------------
// Flash attention, ONE barrier per tile:
// 256 threads / 8 warps (rg = warp&3, ch = warp>>2). QK 16x32.
// PV: own 32 keys from register P-frags (in-iteration);
//     sibling's 32 keys DEFERRED to the next iteration, right after its top
//     barrier (which provides P visibility). V and P triple-buffered to make
//     the deferral race-free; K double-buffered. Q staged in V2 (prologue).
// ---------------------------------------------------------------------------
#define SM_K0   0
#define SM_K1   32768
#define SM_V0   65536
#define SM_V1   98304
#define SM_V2   131072          // prologue Q staging lives here too
#define SM_P0   163840
#define SM_P1   172032
#define SM_P2   180224
#define SM_TOTAL 188416

#define ONESH2 0x3C003C00u

__global__ __launch_bounds__(256) void attn_kernel(
    const int* __restrict__ mask, float* __restrict__ out)
{
    extern __shared__ char smem[];
    const uint32_t sb = (uint32_t)__cvta_generic_to_shared(smem);

    const int tid  = threadIdx.x;
    const int warp = tid >> 5;
    const int lane = tid & 31;
    const int rg   = warp & 3;      // 16-row group
    const int ch   = warp >> 2;     // key/column half (0..1)
    const int b    = blockIdx.y;
    const int q0   = blockIdx.x * 64;

    const int qra = rg * 16 + (lane >> 2);
    const int qrb = qra + 8;
    const int b8  = (lane >> 3) & 1;

    // ---- XOR-addressing bases (loop-invariant) ----
    const uint32_t KA0 = (uint32_t)((ch * 4 + b8) * 1024 + (lane & 7) * 128
                     + (((lane >> 4) * 16) ^ ((lane & 7) * 16)));
    const uint32_t VA0 = (uint32_t)(ch * 16384 + b8 * 1024 + (lane & 7) * 128
                     + (((lane >> 4) * 16) ^ ((lane & 7) * 16)));
    const uint32_t PRA0 = (uint32_t)(rg * 2048 + b8 * 1024 + (lane & 7) * 128
                     + (((lane >> 4) * 16) ^ ((lane & 7) * 16)));
    const uint32_t PWA0 = (uint32_t)(rg * 2048 + (lane >> 2) * 128
                     + ((((lane & 3) * 4) ^ ((lane >> 2) * 16)) ^ (ch * 64)));

    uint32_t soff[8];
    #pragma unroll
    for (int i = 0; i < 8; ++i) {
        int idx = tid + i * 256;
        soff[i] = toff(idx >> 5, (idx & 31) * 8);
    }

    const int* mpa = mask + ((size_t)(b * SS) + q0 + qra) * SS + ch * 32 + 2 * (lane & 3);
    const int* mpb = mpa + (size_t)8 * SS;

    const char* gkb = reinterpret_cast<const char*>(g_k + (size_t)(b * SS) * AA);
    const char* gvb = reinterpret_cast<const char*>(g_v + (size_t)(b * SS) * AA);

    // ---- prologue: stage Q (into V2), K(0), V(0) ----
    {
        const char* gq = reinterpret_cast<const char*>(g_q + (size_t)(b * SS + q0) * AA);
        #pragma unroll
        for (int i = 0; i < 8; ++i) {
            int idx = tid + i * 256;
            size_t go = (size_t)(idx >> 5) * 512 + (idx & 31) * 16;
            cp_async16(sb + SM_V2 + soff[i], gq + go);
            cp_async16(sb + SM_K0 + soff[i], gkb + go);
            cp_async16(sb + SM_V0 + soff[i], gvb + go);
        }
        asm volatile("cp.async.commit_group;\n");
        asm volatile("cp.async.wait_group 0;\n");
        __syncthreads();
    }

    // ---- Q fragments persist in registers (64 regs) ----
    uint32_t qf[16][4];
    {
        int qrow = rg * 16 + (lane & 15);
        #pragma unroll
        for (int ks16 = 0; ks16 < 16; ++ks16)
            ldsm_x4(qf[ks16], sb + SM_V2 + toff(qrow, ks16 * 16 + (lane >> 4) * 8));
    }

    float o[16][4];
    #pragma unroll
    for (int ng = 0; ng < 16; ++ng)
        #pragma unroll
        for (int j = 0; j < 4; ++j) o[ng][j] = 0.f;
    float ol[4] = {0.f, 0.f, 0.f, 0.f};
    const float NEG = -60000.f;

    // buffer rotation state
    uint32_t v_cur = sb + SM_V0, v_nxt = sb + SM_V1, v_thr = sb + SM_V2;
    uint32_t p_cur = sb + SM_P0, p_nxt = sb + SM_P1, p_thr = sb + SM_P2;
    uint32_t v_prev = 0, p_prev = 0;

    for (int t = 0; t < NT; ++t) {
        asm volatile("cp.async.wait_group 0;\n");
        __syncthreads();   // THE barrier: P(t-1) visible, K(t)/V(t) visible

        // ---- deferred sibling-PV of tile t-1 ----
        if (t > 0) {
            #pragma unroll
            for (int j = 0; j < 2; ++j) {
                uint32_t kst = (uint32_t)((1 - ch) * 2 + j);
                uint32_t af[4];
                ldsm_x4(af, p_prev + (PRA0 ^ (kst * 32u)));
                #pragma unroll
                for (int nt = 0; nt < 8; ++nt) {
                    uint32_t bf[4];
                    ldsm_x4_t(bf, v_prev + (VA0 ^ (uint32_t)((kst * 2048)
                                         | ((nt >> 2) * 8192) | ((nt & 3) * 32))));
                    mma_f16(o[nt*2],     af, bf[0], bf[1]);
                    mma_f16(o[nt*2 + 1], af, bf[2], bf[3]);
                }
                mma_f16(ol, af, ONESH2, ONESH2);
            }
        }

        // ---- prefetch K(t+1) and V(t+1) ----
        if (t + 1 < NT) {
            const char* gk = gkb + (size_t)(t + 1) * 32768;
            const char* gv = gvb + (size_t)(t + 1) * 32768;
            uint32_t kb = sb + (((t + 1) & 1) ? SM_K1 : SM_K0);
            #pragma unroll
            for (int i = 0; i < 8; ++i) {
                int idx = tid + i * 256;
                size_t go = (size_t)(idx >> 5) * 512 + (idx & 31) * 16;
                cp_async16(kb + soff[i], gk + go);
                cp_async16(v_nxt + soff[i], gv + go);
            }
        }
        asm volatile("cp.async.commit_group;\n");

        // ---- mask prefetch ----
        const int* ma = mpa + t * 64;
        const int* mb = mpb + t * 64;
        int2 mva[4], mvb[4];
        #pragma unroll
        for (int g = 0; g < 4; ++g) {
            mva[g] = __ldg(reinterpret_cast<const int2*>(ma + g * 8));
            mvb[g] = __ldg(reinterpret_cast<const int2*>(mb + g * 8));
        }

        const uint32_t kcur = sb + ((t & 1) ? SM_K1 : SM_K0);

        // ---- S = Q K^T : 16 rows x 32 keys per warp (4 indep chains) ----
        float s[4][4];
        #pragma unroll
        for (int g = 0; g < 4; ++g)
            #pragma unroll
            for (int j = 0; j < 4; ++j) s[g][j] = 0.f;

        #pragma unroll
        for (int ks16 = 0; ks16 < 16; ++ks16) {
            uint32_t xorc = (uint32_t)(((ks16 >> 2) * 8192) | ((ks16 & 3) * 32));
            uint32_t kf0[4], kf1[4];
            ldsm_x4(kf0, kcur + (KA0 ^ xorc));
            ldsm_x4(kf1, kcur + (KA0 ^ xorc ^ 2048u));
            mma_f16(s[0], qf[ks16], kf0[0], kf0[2]);
            mma_f16(s[1], qf[ks16], kf0[1], kf0[3]);
            mma_f16(s[2], qf[ks16], kf1[0], kf1[2]);
            mma_f16(s[3], qf[ks16], kf1[1], kf1[3]);
        }

        // ---- mask-select, ex2, store P (p_cur); keep packed frags ----
        uint32_t pp[4][2];
        #pragma unroll
        for (int g = 0; g < 4; ++g) {
            uint32_t pa = ex2_f16x2(packh2(mva[g].x ? s[g][0] : NEG,
                                           mva[g].y ? s[g][1] : NEG));
            uint32_t pb = ex2_f16x2(packh2(mvb[g].x ? s[g][2] : NEG,
                                           mvb[g].y ? s[g][3] : NEG));
            uint32_t wa = PWA0 ^ (uint32_t)(g * 16);
            *reinterpret_cast<uint32_t*>(smem + (p_cur - sb) + wa)           = pa;
            *reinterpret_cast<uint32_t*>(smem + (p_cur - sb) + (wa ^ 1024u)) = pb;
            pp[g][0] = pa;
            pp[g][1] = pb;
        }

        // ---- PV over OWN 32 keys: A-frags straight from registers ----
        #pragma unroll
        for (int j = 0; j < 2; ++j) {
            uint32_t af[4] = { pp[2*j][0], pp[2*j][1], pp[2*j+1][0], pp[2*j+1][1] };
            uint32_t kst = (uint32_t)(ch * 2 + j);
            #pragma unroll
            for (int nt = 0; nt < 8; ++nt) {
                uint32_t bf[4];
                ldsm_x4_t(bf, v_cur + (VA0 ^ (uint32_t)((kst * 2048)
                                     | ((nt >> 2) * 8192) | ((nt & 3) * 32))));
                mma_f16(o[nt*2],     af, bf[0], bf[1]);
                mma_f16(o[nt*2 + 1], af, bf[2], bf[3]);
            }
            mma_f16(ol, af, ONESH2, ONESH2);
        }

        // ---- rotate buffers ----
        v_prev = v_cur; p_prev = p_cur;
        uint32_t tv = v_cur; v_cur = v_nxt; v_nxt = v_thr; v_thr = tv;
        uint32_t tp = p_cur; p_cur = p_nxt; p_nxt = p_thr; p_thr = tp;
    }

    // ---- tail: sibling-PV of tile NT-1 ----
    __syncthreads();
    {
        #pragma unroll
        for (int j = 0; j < 2; ++j) {
            uint32_t kst = (uint32_t)((1 - ch) * 2 + j);
            uint32_t af[4];
            ldsm_x4(af, p_prev + (PRA0 ^ (kst * 32u)));
            #pragma unroll
            for (int nt = 0; nt < 8; ++nt) {
                uint32_t bf[4];
                ldsm_x4_t(bf, v_prev + (VA0 ^ (uint32_t)((kst * 2048)
                                     | ((nt >> 2) * 8192) | ((nt & 3) * 32))));
                mma_f16(o[nt*2],     af, bf[0], bf[1]);
                mma_f16(o[nt*2 + 1], af, bf[2], bf[3]);
            }
            mma_f16(ol, af, ONESH2, ONESH2);
        }
    }

    // ---- normalize + write ----
    float inva = 1.f / ol[0];
    float invb = 1.f / ol[2];
    size_t base_a = ((size_t)(b * SS + q0 + qra)) * AA;
    size_t base_b = base_a + (size_t)8 * AA;
    #pragma unroll
    for (int ng = 0; ng < 16; ++ng) {
        int col = ch * 128 + ng * 8 + 2 * (lane & 3);
        float2 va = { o[ng][0] * inva, o[ng][1] * inva };
        float2 vb = { o[ng][2] * invb, o[ng][3] * invb };
        *reinterpret_cast<float2*>(&out[base_a + col]) = va;
        *reinterpret_cast<float2*>(&out[base_b + col]) = vb;
    }
}

// ---------------------------------------------------------------------------
extern "C" void kernel_launch(void* const* d_in, const int* in_sizes, int n_in,
                              void* d_out, int out_size)
{
    const float* x   = (const float*)d_in[0];
    const int*   msk = (const int*)  d_in[1];
    const float* Wq  = (const float*)d_in[2];
    const float* bq  = (const float*)d_in[3];
    const float* Wk  = (const float*)d_in[4];
    const float* bk  = (const float*)d_in[5];
    const float* Wv  = (const float*)d_in[6];
    const float* bv  = (const float*)d_in[7];
    float* out = (float*)d_out;

    convw_kernel<<<192, 256>>>(Wq, Wk, Wv);

    cudaFuncSetAttribute(proj_kernel,
                         cudaFuncAttributeMaxDynamicSharedMemorySize,
                         PJ_TOTAL);
    proj_kernel<<<MM / 128, 512, PJ_TOTAL>>>(x, bq, bk, bv);

    cudaFuncSetAttribute(attn_kernel,
                         cudaFuncAttributeMaxDynamicSharedMemorySize,
                         SM_TOTAL);
    dim3 agrid(SS / 64, BB);
    attn_kernel<<<agrid, 256, SM_TOTAL>>>(msk, out);
}